// round 2
// baseline (speedup 1.0000x reference)
#include <cuda_runtime.h>

// out[b,i,j] = pos_biases[j - i + n - 1]
//            + ts_w[ clamp( floor( log(clip(|f32(t[b,min(i+1,n-1)]) - f32(t[b,j])|, 1, 1e9)) / 0.301 ), 0, nb ) ]
//
// B=8, N=2048, nb=128. Output 8*2048*2048 fp32 = 128 MiB -> HBM-write-bound.
//
// Bucket computation: fast path uses __log2f * (ln2/0.301) (error ~1e-5);
// a guard band of 5e-4 around integer boundaries falls back to a
// correctly-rounded f32 log (double log, rounded to f32, then IEEE f32
// division by 0.301f) which mirrors the reference's f32 log/div sequence.
// x==1 (the j==i+1 diagonal and clipped-to-1 values) is exact on the fast path.

__device__ __forceinline__ float bucket_weight(float tn, int tji,
                                               const float* __restrict__ sw,
                                               int nb) {
    float dt = tn - (float)tji;                       // f32 sub of f32-converted ints (matches ref)
    float x  = fminf(fmaxf(fabsf(dt), 1.0f), 1e9f);   // clip
    // fast path: log(x)/0.301 == log2(x) * (ln2/0.301)
    float q  = __log2f(x) * 2.3028145f;
    int   k  = (int)q;                                // q >= 0, trunc == floor
    float fr = q - (float)k;
    // guard: near a bucket boundary -> recompute with correctly-rounded f32 log
    if (((fr < 5.0e-4f) || (fr > 0.99951f)) && (x != 1.0f)) {
        double ld  = log((double)x);                  // ~0.5 ulp in double
        float  l32 = (float)ld;                       // correctly-rounded f32 log
        float  qf  = __fdiv_rn(l32, 0.301f);          // IEEE f32 divide (matches jnp)
        k = (int)qf;
    }
    k = max(0, min(k, nb));
    return sw[k];
}

__global__ void __launch_bounds__(256)
bias_kernel(const int*   __restrict__ ts,
            const float* __restrict__ pos,
            const float* __restrict__ tsw,
            float*       __restrict__ out,
            int n, int nb) {
    __shared__ float sw[160];  // nb+1 <= 129 in practice

    const int i = blockIdx.x;  // query row
    const int b = blockIdx.y;  // batch

    for (int k = threadIdx.x; k <= nb; k += blockDim.x) sw[k] = tsw[k];
    __syncthreads();

    const int*   trow = ts  + (size_t)b * n;
    const float* prow = pos + (n - 1 - i);            // pos index = j + (n-1-i)
    float*       orow = out + ((size_t)b * n + i) * (size_t)n;

    const float tn = (float)__ldg(&trow[min(i + 1, n - 1)]);

    // each thread handles 4 consecutive j per iteration; n % 4 == 0, 16B aligned
    for (int j = threadIdx.x * 4; j < n; j += blockDim.x * 4) {
        int4 t4 = *reinterpret_cast<const int4*>(trow + j);
        float4 o;
        o.x = bucket_weight(tn, t4.x, sw, nb) + __ldg(prow + j + 0);
        o.y = bucket_weight(tn, t4.y, sw, nb) + __ldg(prow + j + 1);
        o.z = bucket_weight(tn, t4.z, sw, nb) + __ldg(prow + j + 2);
        o.w = bucket_weight(tn, t4.w, sw, nb) + __ldg(prow + j + 3);
        *reinterpret_cast<float4*>(orow + j) = o;
    }
}

extern "C" void kernel_launch(void* const* d_in, const int* in_sizes, int n_in,
                              void* d_out, int out_size) {
    const int*   ts  = (const int*)d_in[0];     // timestamps (B*N) int32
    const float* pos = (const float*)d_in[1];   // pos_biases (2N-1) f32
    const float* tsw = (const float*)d_in[2];   // ts_w (nb+1) f32

    const int n  = (in_sizes[1] + 1) / 2;       // 2N-1 -> N
    const int B  = in_sizes[0] / n;
    const int nb = in_sizes[2] - 1;

    dim3 grid(n, B);
    bias_kernel<<<grid, 256>>>(ts, pos, tsw, (float*)d_out, n, nb);
}